// round 8
// baseline (speedup 1.0000x reference)
#include <cuda_runtime.h>

#define NROWS 32768
#define DCOLS 2048
#define EPS 1e-6f

#define NCTA 148          // <= SM count: all CTAs co-resident => spin barrier safe
#define TPB 256
#define STRIDE4 (DCOLS / 4)   // 512 float4 per row

// Scratch (device globals => no allocation)
__device__ float g_part[NCTA * DCOLS];   // per-CTA column partials (1.2 MB)
__device__ float g_u[DCOLS];
__device__ unsigned g_count = 0;         // barrier arrival counter (returns to 0)
__device__ volatile unsigned g_gen = 0;  // barrier generation (monotonic across replays)

__device__ __forceinline__ void gsync() {
    __syncthreads();
    if (threadIdx.x == 0) {
        unsigned gen = g_gen;
        __threadfence();                          // make prior stores visible
        if (atomicAdd(&g_count, 1u) == NCTA - 1) {
            g_count = 0;
            __threadfence();
            g_gen = gen + 1;                      // release
        } else {
            // Hardened spin: HW nanosleep instead of full-rate polling.
            unsigned ns = 32;
            while (g_gen == gen) {
                __nanosleep(ns);
                if (ns < 1024) ns <<= 1;
            }
        }
        __threadfence();                          // acquire
    }
    __syncthreads();
}

__global__ __launch_bounds__(TPB) void bn_persistent_kernel(const float* __restrict__ x,
                                                            float* __restrict__ out) {
    const int b = blockIdx.x;
    const int t = threadIdx.x;
    // Thread t owns float4 columns c0 = t and c1 = t + 256 (8 scalar columns).
    const int c0 = t, c1 = t + TPB;

    // Row set for this CTA: rows {b, b+148, b+296, ...}
    const int nk = (NROWS - b + NCTA - 1) / NCTA;   // 221 or 222

    const float4* __restrict__ xv = reinterpret_cast<const float4*>(x);
    float4* __restrict__ ov = reinterpret_cast<float4*>(out);

    // ---------- Phase A: accumulate sum of squares over this CTA's rows ----------
    float4 a0 = make_float4(0.f, 0.f, 0.f, 0.f);
    float4 a1 = make_float4(0.f, 0.f, 0.f, 0.f);
    #pragma unroll 4
    for (int k = 0; k < nk; ++k) {
        long long base = (long long)(b + k * NCTA) * STRIDE4;
        float4 v0 = xv[base + c0];
        float4 v1 = xv[base + c1];
        a0.x = fmaf(v0.x, v0.x, a0.x);  a0.y = fmaf(v0.y, v0.y, a0.y);
        a0.z = fmaf(v0.z, v0.z, a0.z);  a0.w = fmaf(v0.w, v0.w, a0.w);
        a1.x = fmaf(v1.x, v1.x, a1.x);  a1.y = fmaf(v1.y, v1.y, a1.y);
        a1.z = fmaf(v1.z, v1.z, a1.z);  a1.w = fmaf(v1.w, v1.w, a1.w);
    }
    {
        float4* pv = reinterpret_cast<float4*>(g_part) + (long long)b * STRIDE4;
        pv[c0] = a0;
        pv[c1] = a1;
    }

    gsync();

    // ---------- Reduce: fold NCTA partials + eps into g_u (CTAs 0..7) ----------
    {
        int col = b * TPB + t;            // only col < 2048 does work (CTAs 0..7)
        if (col < DCOLS) {
            float s = 0.f;
            #pragma unroll 4
            for (int j = 0; j < NCTA; ++j)
                s += g_part[j * DCOLS + col];
            g_u[col] = s + EPS;
        }
    }

    gsync();

    // ---------- Phase B: re-read own rows tail-first (L2-hot), scale, store ----------
    float4 u0 = *reinterpret_cast<const float4*>(g_u + c0 * 4);
    float4 u1 = *reinterpret_cast<const float4*>(g_u + c1 * 4);
    float4 r0 = make_float4(rsqrtf(u0.x), rsqrtf(u0.y), rsqrtf(u0.z), rsqrtf(u0.w));
    float4 r1 = make_float4(rsqrtf(u1.x), rsqrtf(u1.y), rsqrtf(u1.z), rsqrtf(u1.w));

    #pragma unroll 4
    for (int k = nk - 1; k >= 0; --k) {             // reverse: most-recently-read first
        long long base = (long long)(b + k * NCTA) * STRIDE4;
        float4 v0 = __ldcs(&xv[base + c0]);         // streaming: don't re-pollute L2
        float4 v1 = __ldcs(&xv[base + c1]);
        float4 o0, o1;
        o0.x = v0.x * r0.x;  o0.y = v0.y * r0.y;  o0.z = v0.z * r0.z;  o0.w = v0.w * r0.w;
        o1.x = v1.x * r1.x;  o1.y = v1.y * r1.y;  o1.z = v1.z * r1.z;  o1.w = v1.w * r1.w;
        __stcs(&ov[base + c0], o0);                 // streaming write
        __stcs(&ov[base + c1], o1);
    }
}

extern "C" void kernel_launch(void* const* d_in, const int* in_sizes, int n_in,
                              void* d_out, int out_size) {
    const float* x = (const float*)d_in[0];
    float* out = (float*)d_out;
    bn_persistent_kernel<<<NCTA, TPB>>>(x, out);
}

// round 10
// speedup vs baseline: 1.7427x; 1.7427x over previous
#include <cuda_runtime.h>

#define NROWS 32768
#define DCOLS 2048
#define EPS 1e-6f

#define NCTA 148              // <= SM count: all CTAs co-resident => spin barrier safe
#define TPB 1024              // 32 warps/SM: enough MLP to saturate DRAM
#define STRIDE4 (DCOLS / 4)   // 512 float4 per row

// Scratch (device globals => no allocation)
__device__ float g_part[2 * NCTA * DCOLS];   // per-(CTA,parity) column partials (2.4 MB)
__device__ float g_u[DCOLS];
__device__ unsigned g_count = 0;             // barrier arrival counter (returns to 0)
__device__ volatile unsigned g_gen = 0;      // barrier generation (monotonic across replays)

__device__ __forceinline__ void gsync() {
    __syncthreads();
    if (threadIdx.x == 0) {
        unsigned gen = g_gen;
        __threadfence();
        if (atomicAdd(&g_count, 1u) == NCTA - 1) {
            g_count = 0;
            __threadfence();
            g_gen = gen + 1;                  // release
        } else {
            unsigned ns = 32;
            while (g_gen == gen) {            // HW-sleep spin; all CTAs resident
                __nanosleep(ns);
                if (ns < 1024) ns <<= 1;
            }
        }
        __threadfence();                      // acquire
    }
    __syncthreads();
}

__global__ __launch_bounds__(TPB) void bn_persistent_kernel(const float* __restrict__ x,
                                                            float* __restrict__ out) {
    const int b = blockIdx.x;
    const int t = threadIdx.x;
    const int c = t & (STRIDE4 - 1);        // float4 column 0..511
    const int p = t >> 9;                   // row parity 0/1

    // Rows for this CTA: {b + k*NCTA, k = 0..nk-1}; this thread takes k ≡ p (mod 2).
    const int nk = (NROWS - b + NCTA - 1) / NCTA;   // 221 or 222

    const float4* __restrict__ xv = reinterpret_cast<const float4*>(x);
    float4* __restrict__ ov = reinterpret_cast<float4*>(out);

    // ---------- Phase A: accumulate sum of squares over this thread's rows ----------
    float ax = 0.f, ay = 0.f, az = 0.f, aw = 0.f;
    #pragma unroll 8
    for (int k = p; k < nk; k += 2) {
        float4 v = xv[(long long)(b + k * NCTA) * STRIDE4 + c];
        ax = fmaf(v.x, v.x, ax);
        ay = fmaf(v.y, v.y, ay);
        az = fmaf(v.z, v.z, az);
        aw = fmaf(v.w, v.w, aw);
    }
    reinterpret_cast<float4*>(g_part)[(long long)(2 * b + p) * STRIDE4 + c] =
        make_float4(ax, ay, az, aw);

    gsync();

    // ---------- Reduce: fold 2*NCTA partials + eps into g_u (CTAs 0..1) ----------
    {
        int col = b * TPB + t;               // only col < 2048 works (CTAs 0,1)
        if (col < DCOLS) {
            float s = 0.f;
            #pragma unroll 8
            for (int j = 0; j < 2 * NCTA; ++j)
                s += g_part[j * DCOLS + col];
            g_u[col] = s + EPS;
        }
    }

    gsync();

    // ---------- Phase B: re-read own rows tail-first (L2-hot), scale, store ----------
    const float4 u = *reinterpret_cast<const float4*>(g_u + c * 4);   // 8 KB, cached
    const float rx = rsqrtf(u.x), ry = rsqrtf(u.y), rz = rsqrtf(u.z), rw = rsqrtf(u.w);

    int kmax = nk - 1;
    if ((kmax & 1) != p) --kmax;             // largest k with k ≡ p (mod 2)

    #pragma unroll 8
    for (int k = kmax; k >= 0; k -= 2) {     // reverse: most-recently-read rows first
        long long idx = (long long)(b + k * NCTA) * STRIDE4 + c;
        float4 v = __ldcs(&xv[idx]);         // streaming: no future reuse
        float4 o;
        o.x = v.x * rx;  o.y = v.y * ry;  o.z = v.z * rz;  o.w = v.w * rw;
        __stcs(&ov[idx], o);                 // streaming write
    }
}

extern "C" void kernel_launch(void* const* d_in, const int* in_sizes, int n_in,
                              void* d_out, int out_size) {
    const float* x = (const float*)d_in[0];
    float* out = (float*)d_out;
    bn_persistent_kernel<<<NCTA, TPB>>>(x, out);
}

// round 16
// speedup vs baseline: 1.9989x; 1.1470x over previous
#include <cuda_runtime.h>

#define NROWS 32768
#define DCOLS 2048
#define EPS 1e-6f

#define ROWS_PER_CTA 128
#define NBY (NROWS / ROWS_PER_CTA)   // 256 partial slabs
#define STRIDE4 (DCOLS / 4)          // 512 float4 per row

// Scratch (device globals => no allocation):
__device__ float g_part[NBY * DCOLS];  // 2 MB of per-block partial sums
__device__ float g_u[DCOLS];           // final per-column rsqrt argument

// ---------------------------------------------------------------------------
// Pass 1: column partial sums of squares (R6-proven: 42.8us, 80% DRAM).
// grid = (2, 256), block = 256. Each (bx,by) block owns a 1024-col x 128-row slab.
// ---------------------------------------------------------------------------
__global__ __launch_bounds__(256) void colsumsq_kernel(const float* __restrict__ x) {
    const int col4 = blockIdx.x * blockDim.x + threadIdx.x;
    const int row0 = blockIdx.y * ROWS_PER_CTA;

    const float4* __restrict__ xv = reinterpret_cast<const float4*>(x);
    long long base = (long long)row0 * STRIDE4 + col4;

    float ax = 0.f, ay = 0.f, az = 0.f, aw = 0.f;
    #pragma unroll 16
    for (int r = 0; r < ROWS_PER_CTA; ++r) {
        float4 v = xv[base + (long long)r * STRIDE4];
        ax = fmaf(v.x, v.x, ax);
        ay = fmaf(v.y, v.y, ay);
        az = fmaf(v.z, v.z, az);
        aw = fmaf(v.w, v.w, aw);
    }

    reinterpret_cast<float4*>(g_part)[(long long)blockIdx.y * STRIDE4 + col4] =
        make_float4(ax, ay, az, aw);
}

// ---------------------------------------------------------------------------
// Pass 1b: fold NBY partials + eps into g_u. __ldcs so the 2 MB of partials
// doesn't evict the L2-hot tail of x that pass 2 wants. grid = 8, block = 256.
// ---------------------------------------------------------------------------
__global__ __launch_bounds__(256) void reduce_kernel() {
    const int col = blockIdx.x * blockDim.x + threadIdx.x;    // 0..2047
    float s = 0.f;
    #pragma unroll 16
    for (int j = 0; j < NBY; ++j)
        s += __ldcs(&g_part[j * DCOLS + col]);
    g_u[col] = s + EPS;
}

// ---------------------------------------------------------------------------
// Pass 2: out[n,d] = x[n,d] * rsqrt(u[d]).
// Each block owns a contiguous 16 KB line (1024 float4); each thread issues 4
// independent float4 loads (MLP=4) then 4 stores. Block order REVERSED so the
// first waves read the tail of x still L2-resident from pass 1; streaming
// hints keep the 256 MB output write from evicting it.
// grid = 16384, block = 256.
// ---------------------------------------------------------------------------
__global__ __launch_bounds__(256) void scale_kernel(const float* __restrict__ x,
                                                    float* __restrict__ out) {
    const int blk = gridDim.x - 1 - blockIdx.x;               // reversed schedule
    const long long base = (long long)blk * 1024;             // float4 units
    const int t = threadIdx.x;

    const float4* __restrict__ xv = reinterpret_cast<const float4*>(x);
    float4* __restrict__ ov = reinterpret_cast<float4*>(out);

    // base is a multiple of 1024 (= 2 rows), so lanes j=0,2 hit col4 = t and
    // lanes j=1,3 hit col4 = t + 256. Two u vectors per thread, L1/L2 cached.
    const float4 u0 = *reinterpret_cast<const float4*>(g_u + t * 4);
    const float4 u1 = *reinterpret_cast<const float4*>(g_u + (t + 256) * 4);
    const float r0x = rsqrtf(u0.x), r0y = rsqrtf(u0.y), r0z = rsqrtf(u0.z), r0w = rsqrtf(u0.w);
    const float r1x = rsqrtf(u1.x), r1y = rsqrtf(u1.y), r1z = rsqrtf(u1.z), r1w = rsqrtf(u1.w);

    // Front-batched independent loads (MLP = 4)
    float4 v0 = __ldcs(&xv[base + t]);
    float4 v1 = __ldcs(&xv[base + t + 256]);
    float4 v2 = __ldcs(&xv[base + t + 512]);
    float4 v3 = __ldcs(&xv[base + t + 768]);

    float4 o0, o1, o2, o3;
    o0.x = v0.x * r0x;  o0.y = v0.y * r0y;  o0.z = v0.z * r0z;  o0.w = v0.w * r0w;
    o1.x = v1.x * r1x;  o1.y = v1.y * r1y;  o1.z = v1.z * r1z;  o1.w = v1.w * r1w;
    o2.x = v2.x * r0x;  o2.y = v2.y * r0y;  o2.z = v2.z * r0z;  o2.w = v2.w * r0w;
    o3.x = v3.x * r1x;  o3.y = v3.y * r1y;  o3.z = v3.z * r1z;  o3.w = v3.w * r1w;

    __stcs(&ov[base + t],       o0);
    __stcs(&ov[base + t + 256], o1);
    __stcs(&ov[base + t + 512], o2);
    __stcs(&ov[base + t + 768], o3);
}

extern "C" void kernel_launch(void* const* d_in, const int* in_sizes, int n_in,
                              void* d_out, int out_size) {
    const float* x = (const float*)d_in[0];
    float* out = (float*)d_out;

    dim3 grid1(STRIDE4 / 256, NBY);                       // (2, 256) = 512 CTAs
    colsumsq_kernel<<<grid1, 256>>>(x);

    reduce_kernel<<<DCOLS / 256, 256>>>();                // 8 CTAs

    const long long nvec4 = (long long)NROWS * DCOLS / 4; // 16,777,216
    int blocks2 = (int)(nvec4 / 1024);                    // 16,384
    scale_kernel<<<blocks2, 256>>>(x, out);
}